// round 4
// baseline (speedup 1.0000x reference)
#include <cuda_runtime.h>
#include <math.h>

#define BATCH 4
#define SEQ 4096
#define NH 16
#define HD 64
#define DIM 1024
#define BH (BATCH*NH)          // 64
#define CHUNK 64
#define NCHUNK (SEQ/CHUNK)     // 64
#define MTOT (BATCH*SEQ)       // 16384
#define FSCALE 0.35355339059327373f   // 64^-0.25

// ---------------- scratch (static device globals; no allocation) ----------------
__device__ float g_qkv [ (size_t)MTOT * 3 * DIM ];          // 192 MB
__device__ float g_qf  [ (size_t)BH * SEQ * HD ];           // 64 MB  [bh][t][d]
__device__ float g_kf  [ (size_t)BH * SEQ * HD ];
__device__ float g_vf  [ (size_t)BH * SEQ * HD ];
__device__ float g_Skv [ (size_t)BH * NCHUNK * HD * HD ];   // 64 MB  per-chunk k^T v
__device__ float g_Pkv [ (size_t)BH * NCHUNK * HD * HD ];   // exclusive prefix
__device__ float g_Sks [ (size_t)BH * NCHUNK * HD ];
__device__ float g_Pks [ (size_t)BH * NCHUNK * HD ];
__device__ float g_attn[ (size_t)MTOT * DIM ];              // 64 MB  [b*N+t][h*64+m]

// ---------------- generic fp32 SGEMM: C[M,N] = A[M,K] @ B[K,N], all row-major ----
// BM=BN=128, BK=8, 256 threads, 8x8 microtile. M,N multiples of 128, K multiple of 8.
__global__ __launch_bounds__(256) void sgemm128(const float* __restrict__ A,
                                                const float* __restrict__ Bm,
                                                float* __restrict__ C,
                                                int M, int N, int K)
{
    __shared__ __align__(16) float As[8][128];
    __shared__ __align__(16) float Bs[8][128];

    const int tid = threadIdx.x;
    const int m0 = blockIdx.y * 128;
    const int n0 = blockIdx.x * 128;

    const int arow = tid >> 1;            // 0..127
    const int acol = (tid & 1) * 4;       // 0 or 4
    const int brow = tid >> 5;            // 0..7
    const int bcol = (tid & 31) * 4;      // 0..124

    const float* Aptr = A + (size_t)(m0 + arow) * K + acol;
    const float* Bptr = Bm + (size_t)brow * N + n0 + bcol;

    const int ty = tid >> 4, tx = tid & 15;
    float acc[8][8];
#pragma unroll
    for (int i = 0; i < 8; i++)
#pragma unroll
        for (int j = 0; j < 8; j++) acc[i][j] = 0.f;

    for (int k0 = 0; k0 < K; k0 += 8) {
        float4 a4 = *(const float4*)(Aptr + k0);
        float4 b4 = *(const float4*)(Bptr + (size_t)k0 * N);
        __syncthreads();
        As[acol + 0][arow] = a4.x;
        As[acol + 1][arow] = a4.y;
        As[acol + 2][arow] = a4.z;
        As[acol + 3][arow] = a4.w;
        *(float4*)&Bs[brow][bcol] = b4;
        __syncthreads();
#pragma unroll
        for (int k = 0; k < 8; k++) {
            float af[8], bf[8];
            *(float4*)&af[0] = *(float4*)&As[k][ty * 8];
            *(float4*)&af[4] = *(float4*)&As[k][ty * 8 + 4];
            *(float4*)&bf[0] = *(float4*)&Bs[k][tx * 8];
            *(float4*)&bf[4] = *(float4*)&Bs[k][tx * 8 + 4];
#pragma unroll
            for (int i = 0; i < 8; i++)
#pragma unroll
                for (int j = 0; j < 8; j++)
                    acc[i][j] += af[i] * bf[j];
        }
    }

#pragma unroll
    for (int i = 0; i < 8; i++) {
        float* cp = C + (size_t)(m0 + ty * 8 + i) * N + n0 + tx * 8;
        *(float4*)cp       = make_float4(acc[i][0], acc[i][1], acc[i][2], acc[i][3]);
        *(float4*)(cp + 4) = make_float4(acc[i][4], acc[i][5], acc[i][6], acc[i][7]);
    }
}

// ---------------- RoPE + ELU feature map + layout change -------------------------
// one thread per (b,t,h,j) with j in [0,32): handles the rope pair (j, j+32) for q,k
// and copies v pair. Writes [bh][t][d] layout.
__global__ __launch_bounds__(256) void featmap_kernel()
{
    int idx = blockIdx.x * blockDim.x + threadIdx.x;   // < 2^23
    int j = idx & 31;
    int h = (idx >> 5) & 15;
    int t = (idx >> 9) & 4095;
    int b = idx >> 21;

    const float* row = g_qkv + (size_t)(b * SEQ + t) * 3072 + h * 64;
    float q1 = row[j],        q2 = row[j + 32];
    float k1 = row[1024 + j], k2 = row[1024 + j + 32];
    float v1 = row[2048 + j], v2 = row[2048 + j + 32];

    // inv_freq = 10000^(-j/32) ; angle = t * inv_freq (fp32, same as reference)
    float inv = expf(-0.28782313662425572f * (float)j);   // ln(10000)/32
    float ang = (float)t * inv;
    float s, c;
    sincosf(ang, &s, &c);

    float qa = q1 * c - q2 * s, qb = q1 * s + q2 * c;
    float ka = k1 * c - k2 * s, kb = k1 * s + k2 * c;

    qa *= FSCALE; qb *= FSCALE; ka *= FSCALE; kb *= FSCALE;
    qa = (qa > 0.f) ? qa + 1.f : expf(qa);   // elu(z)+1
    qb = (qb > 0.f) ? qb + 1.f : expf(qb);
    ka = (ka > 0.f) ? ka + 1.f : expf(ka);
    kb = (kb > 0.f) ? kb + 1.f : expf(kb);

    size_t o = ((size_t)(b * NH + h) * SEQ + t) * 64 + j;
    g_qf[o] = qa; g_qf[o + 32] = qb;
    g_kf[o] = ka; g_kf[o + 32] = kb;
    g_vf[o] = v1; g_vf[o + 32] = v2;
}

// ---------------- per-chunk local sums: S_kv = K^T V (64x64), S_ks = sum k -------
__global__ __launch_bounds__(256) void chunksum_kernel()
{
    const int c = blockIdx.x, bh = blockIdx.y;
    const int tid = threadIdx.x;
    __shared__ __align__(16) float ks[CHUNK][HD];
    __shared__ __align__(16) float vs[CHUNK][HD];

    const float* Kg = g_kf + ((size_t)bh * SEQ + c * CHUNK) * HD;
    const float* Vg = g_vf + ((size_t)bh * SEQ + c * CHUNK) * HD;

    const int row = tid >> 2, f0 = tid & 3;
#pragma unroll
    for (int i = 0; i < 4; i++) {
        int f = (f0 + i * 4) * 4;
        *(float4*)&ks[row][f] = *(const float4*)(Kg + row * 64 + f);
        *(float4*)&vs[row][f] = *(const float4*)(Vg + row * 64 + f);
    }
    __syncthreads();

    const int m = tid & 63;
    const int dbase = (tid >> 6) * 16;
    float acc[16];
#pragma unroll
    for (int i = 0; i < 16; i++) acc[i] = 0.f;

    for (int t = 0; t < CHUNK; t++) {
        float v = vs[t][m];
#pragma unroll
        for (int w = 0; w < 4; w++) {
            float4 kk = *(float4*)&ks[t][dbase + w * 4];
            acc[w * 4 + 0] += kk.x * v;
            acc[w * 4 + 1] += kk.y * v;
            acc[w * 4 + 2] += kk.z * v;
            acc[w * 4 + 3] += kk.w * v;
        }
    }

    float* S = g_Skv + ((size_t)bh * NCHUNK + c) * (HD * HD);
#pragma unroll
    for (int d = 0; d < 16; d++)
        S[(dbase + d) * 64 + m] = acc[d];

    if (tid < 64) {
        float s = 0.f;
        for (int t = 0; t < CHUNK; t++) s += ks[t][tid];
        g_Sks[((size_t)bh * NCHUNK + c) * HD + tid] = s;
    }
}

// ---------------- exclusive prefix over chunks ----------------------------------
__global__ __launch_bounds__(256) void prefix_kernel()
{
    const int bh = blockIdx.x;
    const int tid = threadIdx.x;
    const size_t base0 = (size_t)bh * NCHUNK * HD * HD;
    const int e0 = tid * 16;

    float4 run[4];
#pragma unroll
    for (int w = 0; w < 4; w++) run[w] = make_float4(0.f, 0.f, 0.f, 0.f);

    for (int c = 0; c < NCHUNK; c++) {
        size_t base = base0 + (size_t)c * (HD * HD) + e0;
#pragma unroll
        for (int w = 0; w < 4; w++) {
            float4 s = *(const float4*)(g_Skv + base + w * 4);
            *(float4*)(g_Pkv + base + w * 4) = run[w];
            run[w].x += s.x; run[w].y += s.y; run[w].z += s.z; run[w].w += s.w;
        }
    }
    if (tid < 64) {
        float r = 0.f;
        for (int c = 0; c < NCHUNK; c++) {
            size_t i = ((size_t)bh * NCHUNK + c) * HD + tid;
            g_Pks[i] = r;
            r += g_Sks[i];
        }
    }
}

// ---------------- main chunk attention ------------------------------------------
// out[t][m] = ( mask(Q K^T) V + Q P_kv )[t][m] / max(rowsum(mask(QK^T)) + Q.P_ks, 1e-6)
__global__ __launch_bounds__(256) void attn_kernel()
{
    const int c = blockIdx.x, bh = blockIdx.y;
    const int tid = threadIdx.x;
    extern __shared__ float sm[];
    float* Qt   = sm;                    // [64][68] transposed (d-major)
    float* Kt   = Qt + 64 * 68;
    float* At   = Kt + 64 * 68;          // [tj][ti] (transposed scores)
    float* Vs   = At + 64 * 68;          // [64][64]
    float* Ps   = Vs + 64 * 64;          // [d][m]
    float* pks  = Ps + 64 * 64;          // [64]
    float* dinv = pks + 64;              // [64]

    const int t0 = c * CHUNK;
    const float* Qg   = g_qf + ((size_t)bh * SEQ + t0) * HD;
    const float* Kg   = g_kf + ((size_t)bh * SEQ + t0) * HD;
    const float* Vg   = g_vf + ((size_t)bh * SEQ + t0) * HD;
    const float* Pg   = g_Pkv + ((size_t)bh * NCHUNK + c) * (HD * HD);
    const float* pksg = g_Pks + ((size_t)bh * NCHUNK + c) * HD;

    const int row = tid >> 2, f0 = tid & 3;
#pragma unroll
    for (int i = 0; i < 4; i++) {
        int d = (f0 + i * 4) * 4;
        float4 q4 = *(const float4*)(Qg + row * 64 + d);
        Qt[(d + 0) * 68 + row] = q4.x;
        Qt[(d + 1) * 68 + row] = q4.y;
        Qt[(d + 2) * 68 + row] = q4.z;
        Qt[(d + 3) * 68 + row] = q4.w;
        float4 k4 = *(const float4*)(Kg + row * 64 + d);
        Kt[(d + 0) * 68 + row] = k4.x;
        Kt[(d + 1) * 68 + row] = k4.y;
        Kt[(d + 2) * 68 + row] = k4.z;
        Kt[(d + 3) * 68 + row] = k4.w;
        *(float4*)&Vs[row * 64 + d] = *(const float4*)(Vg + row * 64 + d);
        *(float4*)&Ps[row * 64 + d] = *(const float4*)(Pg + row * 64 + d);
    }
    if (tid < 64) pks[tid] = pksg[tid];
    __syncthreads();

    const int ty = tid >> 4, tx = tid & 15;
    const int rb = ty * 4, cb = tx * 4;

    // Phase A: scores A[ti][tj] = q_ti . k_tj
    float a[4][4];
#pragma unroll
    for (int i = 0; i < 4; i++)
#pragma unroll
        for (int j = 0; j < 4; j++) a[i][j] = 0.f;

    for (int d = 0; d < 64; d++) {
        float4 q4 = *(float4*)&Qt[d * 68 + rb];
        float4 k4 = *(float4*)&Kt[d * 68 + cb];
        float qv[4] = {q4.x, q4.y, q4.z, q4.w};
        float kv[4] = {k4.x, k4.y, k4.z, k4.w};
#pragma unroll
        for (int i = 0; i < 4; i++)
#pragma unroll
            for (int j = 0; j < 4; j++)
                a[i][j] += qv[i] * kv[j];
    }
    // store transposed with causal mask (tj <= ti kept, incl diagonal)
#pragma unroll
    for (int i = 0; i < 4; i++)
#pragma unroll
        for (int j = 0; j < 4; j++) {
            int ti = rb + i, tj = cb + j;
            At[tj * 68 + ti] = (tj <= ti) ? a[i][j] : 0.f;
        }
    __syncthreads();

    // denominators
    if (tid < 64) {
        float s = 0.f;
        for (int tj = 0; tj < 64; tj++) s += At[tj * 68 + tid];
        for (int d = 0; d < 64; d++) s += Qt[d * 68 + tid] * pks[d];
        dinv[tid] = 1.0f / fmaxf(s, 1e-6f);
    }
    __syncthreads();

    // Phase B: out = A_masked @ V + Q @ P_kv
    float o[4][4];
#pragma unroll
    for (int i = 0; i < 4; i++)
#pragma unroll
        for (int j = 0; j < 4; j++) o[i][j] = 0.f;

    for (int tj = 0; tj < 64; tj++) {
        float4 a4 = *(float4*)&At[tj * 68 + rb];
        float4 v4 = *(float4*)&Vs[tj * 64 + cb];
        float av[4] = {a4.x, a4.y, a4.z, a4.w};
        float vv[4] = {v4.x, v4.y, v4.z, v4.w};
#pragma unroll
        for (int i = 0; i < 4; i++)
#pragma unroll
            for (int j = 0; j < 4; j++)
                o[i][j] += av[i] * vv[j];
    }
    for (int d = 0; d < 64; d++) {
        float4 q4 = *(float4*)&Qt[d * 68 + rb];
        float4 p4 = *(float4*)&Ps[d * 64 + cb];
        float qv[4] = {q4.x, q4.y, q4.z, q4.w};
        float pv[4] = {p4.x, p4.y, p4.z, p4.w};
#pragma unroll
        for (int i = 0; i < 4; i++)
#pragma unroll
            for (int j = 0; j < 4; j++)
                o[i][j] += qv[i] * pv[j];
    }

    const int b = bh >> 4, h = bh & 15;
#pragma unroll
    for (int i = 0; i < 4; i++) {
        int ti = rb + i;
        float di = dinv[ti];
        float* outp = g_attn + (size_t)(b * SEQ + t0 + ti) * DIM + h * 64 + cb;
        *(float4*)outp = make_float4(o[i][0] * di, o[i][1] * di, o[i][2] * di, o[i][3] * di);
    }
}

// ---------------- launch ---------------------------------------------------------
extern "C" void kernel_launch(void* const* d_in, const int* in_sizes, int n_in,
                              void* d_out, int out_size)
{
    const float* x     = (const float*)d_in[0];
    const float* w_qkv = (const float*)d_in[1];
    const float* w_out = (const float*)d_in[2];
    float* out = (float*)d_out;

    float* qkv;  cudaGetSymbolAddress((void**)&qkv,  g_qkv);
    float* attn; cudaGetSymbolAddress((void**)&attn, g_attn);

    // 1) QKV projection: [16384,1024] @ [1024,3072]
    sgemm128<<<dim3(3 * DIM / 128, MTOT / 128), 256>>>(x, w_qkv, qkv, MTOT, 3 * DIM, DIM);

    // 2) RoPE + ELU feature map + layout to [bh][t][d]
    featmap_kernel<<<(BATCH * SEQ * NH * 32) / 256, 256>>>();

    // 3) per-chunk K^T V and sum(k)
    chunksum_kernel<<<dim3(NCHUNK, BH), 256>>>();

    // 4) exclusive prefix over chunks
    prefix_kernel<<<BH, 256>>>();

    // 5) chunk attention (intra + inter + denom) -> g_attn in [b*N+t][h*64+m] layout
    const int attn_smem = (64 * 68 * 3 + 64 * 64 * 2 + 128) * 4;  // 85504 B
    cudaFuncSetAttribute(attn_kernel, cudaFuncAttributeMaxDynamicSharedMemorySize, attn_smem);
    attn_kernel<<<dim3(NCHUNK, BH), 256, attn_smem>>>();

    // 6) output projection: [16384,1024] @ [1024,1024]
    sgemm128<<<dim3(DIM / 128, MTOT / 128), 256>>>(attn, w_out, out, MTOT, DIM, DIM);
}

// round 6
// speedup vs baseline: 2.5056x; 2.5056x over previous
#include <cuda_runtime.h>
#include <cuda_bf16.h>
#include <math.h>
#include <stdint.h>

#define BATCH 4
#define SEQ 4096
#define NH 16
#define HD 64
#define DIM 1024
#define BH (BATCH*NH)          // 64
#define CHUNK 64
#define NCHUNK (SEQ/CHUNK)     // 64
#define MTOT (BATCH*SEQ)       // 16384
#define FSCALE 0.35355339059327373f   // 64^-0.25

// ================= helpers =================
__device__ __forceinline__ uint32_t smem_u32(const void* p) {
    uint32_t a;
    asm("{ .reg .u64 t; cvta.to.shared.u64 t, %1; cvt.u32.u64 %0, t; }" : "=r"(a) : "l"(p));
    return a;
}
#define SW128(off) ((off) ^ (((off) >> 3) & 0x70))

__device__ __forceinline__ void cp16(uint32_t sa, const void* g) {
    asm volatile("cp.async.cg.shared.global [%0], [%1], 16;\n" :: "r"(sa), "l"(g) : "memory");
}
#define CP_COMMIT()  asm volatile("cp.async.commit_group;\n" ::: "memory")
#define CP_WAIT(n)   asm volatile("cp.async.wait_group %0;\n" :: "n"(n) : "memory")

__device__ __forceinline__ void ldsm4(uint32_t* r, uint32_t addr) {
    asm volatile("ldmatrix.sync.aligned.m8n8.x4.shared.b16 {%0,%1,%2,%3}, [%4];"
        : "=r"(r[0]), "=r"(r[1]), "=r"(r[2]), "=r"(r[3]) : "r"(addr));
}
__device__ __forceinline__ void ldsm2(uint32_t* r, uint32_t addr) {
    asm volatile("ldmatrix.sync.aligned.m8n8.x2.shared.b16 {%0,%1}, [%2];"
        : "=r"(r[0]), "=r"(r[1]) : "r"(addr));
}
__device__ __forceinline__ void mma_bf16(float* c, const uint32_t* a, const uint32_t* b) {
    asm volatile(
        "mma.sync.aligned.m16n8k16.row.col.f32.bf16.bf16.f32 "
        "{%0,%1,%2,%3}, {%4,%5,%6,%7}, {%8,%9}, {%0,%1,%2,%3};"
        : "+f"(c[0]), "+f"(c[1]), "+f"(c[2]), "+f"(c[3])
        : "r"(a[0]), "r"(a[1]), "r"(a[2]), "r"(a[3]), "r"(b[0]), "r"(b[1]));
}

// ================= scratch =================
__device__ float g_qkv [ (size_t)MTOT * 3 * DIM ];
__device__ float g_qf  [ (size_t)BH * SEQ * HD ];
__device__ float g_kf  [ (size_t)BH * SEQ * HD ];
__device__ float g_vf  [ (size_t)BH * SEQ * HD ];
__device__ float g_Skv [ (size_t)BH * NCHUNK * HD * HD ];
__device__ float g_Pkv [ (size_t)BH * NCHUNK * HD * HD ];
__device__ float g_Sks [ (size_t)BH * NCHUNK * HD ];
__device__ float g_Pks [ (size_t)BH * NCHUNK * HD ];
__device__ __nv_bfloat16 g_xhi [ (size_t)MTOT * DIM ];
__device__ __nv_bfloat16 g_xlo [ (size_t)MTOT * DIM ];
__device__ __nv_bfloat16 g_wqhi[ (size_t)3 * DIM * DIM ];   // transposed [3072][1024]
__device__ __nv_bfloat16 g_wqlo[ (size_t)3 * DIM * DIM ];
__device__ __nv_bfloat16 g_wohi[ (size_t)DIM * DIM ];       // transposed [1024][1024]
__device__ __nv_bfloat16 g_wolo[ (size_t)DIM * DIM ];
__device__ __nv_bfloat16 g_ahi [ (size_t)MTOT * DIM ];
__device__ __nv_bfloat16 g_alo [ (size_t)MTOT * DIM ];

// ================= split kernels =================
__global__ __launch_bounds__(256) void split_kernel(const float* __restrict__ in,
                                                    __nv_bfloat16* __restrict__ hi,
                                                    __nv_bfloat16* __restrict__ lo)
{
    size_t i = ((size_t)blockIdx.x * 256 + threadIdx.x) * 4;
    float4 v = *(const float4*)(in + i);
    float a[4] = {v.x, v.y, v.z, v.w};
    __nv_bfloat16 h[4], l[4];
#pragma unroll
    for (int j = 0; j < 4; j++) {
        h[j] = __float2bfloat16(a[j]);
        l[j] = __float2bfloat16(a[j] - __bfloat162float(h[j]));
    }
    *(uint2*)(hi + i) = *(uint2*)h;
    *(uint2*)(lo + i) = *(uint2*)l;
}

// transpose + split: W [K][N] fp32 -> out [N][K] bf16 hi/lo
__global__ __launch_bounds__(256) void tsplit_kernel(const float* __restrict__ W,
                                                     __nv_bfloat16* __restrict__ hi,
                                                     __nv_bfloat16* __restrict__ lo,
                                                     int K, int N)
{
    __shared__ float t[32][33];
    int n0 = blockIdx.x * 32, k0 = blockIdx.y * 32;
    int tx = threadIdx.x, ty = threadIdx.y;   // 32 x 8
#pragma unroll
    for (int i = 0; i < 4; i++)
        t[ty + i * 8][tx] = W[(size_t)(k0 + ty + i * 8) * N + n0 + tx];
    __syncthreads();
#pragma unroll
    for (int i = 0; i < 4; i++) {
        float v = t[tx][ty + i * 8];
        __nv_bfloat16 h = __float2bfloat16(v);
        __nv_bfloat16 l = __float2bfloat16(v - __bfloat162float(h));
        size_t o = (size_t)(n0 + ty + i * 8) * K + k0 + tx;
        hi[o] = h; lo[o] = l;
    }
}

// ================= mma.sync bf16x3 GEMM =================
// C[M,Ncols] = A[M,1024] @ W[1024,Ncols]; A bf16 hi/lo row-major [M][1024],
// W transposed bf16 hi/lo [Ncols][1024]. Tile 128x128, KC=64, double buffer.
#define TILE_BYTES (128 * 64 * 2)           // 16 KB (128 rows x 128 B)
#define STAGE_BYTES (4 * TILE_BYTES)        // 64 KB
#define SMEM_STG0 1024
#define GEMM_SMEM (SMEM_STG0 + 2 * STAGE_BYTES)
#define OFF_AHI 0
#define OFF_ALO TILE_BYTES
#define OFF_BHI (2 * TILE_BYTES)
#define OFF_BLO (3 * TILE_BYTES)

__device__ __forceinline__ void load_chunk(uint32_t stg,
    const __nv_bfloat16* __restrict__ Ahi, const __nv_bfloat16* __restrict__ Alo,
    const __nv_bfloat16* __restrict__ Bhi, const __nv_bfloat16* __restrict__ Blo,
    int m0, int n0, int k0, int tid)
{
#pragma unroll
    for (int i = 0; i < 4; i++) {
        int idx = tid + i * 256;
        int row = idx >> 3, cv = idx & 7;
        uint32_t sw = SW128((uint32_t)(row * 128 + cv * 16));
        size_t ao = (size_t)(m0 + row) * 1024 + k0 + cv * 8;
        size_t bo = (size_t)(n0 + row) * 1024 + k0 + cv * 8;
        cp16(stg + OFF_AHI + sw, Ahi + ao);
        cp16(stg + OFF_ALO + sw, Alo + ao);
        cp16(stg + OFF_BHI + sw, Bhi + bo);
        cp16(stg + OFF_BLO + sw, Blo + bo);
    }
}

__global__ __launch_bounds__(256, 1) void gemm_tc(
    const __nv_bfloat16* __restrict__ Ahi, const __nv_bfloat16* __restrict__ Alo,
    const __nv_bfloat16* __restrict__ Bhi, const __nv_bfloat16* __restrict__ Blo,
    float* __restrict__ C, int Ncols)
{
    extern __shared__ __align__(16) char smem[];
    const uint32_t sb = smem_u32(smem) + SMEM_STG0;
    const int tid = threadIdx.x;
    const int lane = tid & 31, wid = tid >> 5;
    const int wm = (wid & 1) * 64;      // warp m offset within 128
    const int wn = (wid >> 1) * 32;     // warp n offset within 128
    const int m0 = blockIdx.y * 128;
    const int n0 = blockIdx.x * 128;

    float acc[4][4][4];
#pragma unroll
    for (int i = 0; i < 4; i++)
#pragma unroll
        for (int j = 0; j < 4; j++)
#pragma unroll
            for (int r = 0; r < 4; r++) acc[i][j][r] = 0.f;

    // lane-dependent ldmatrix row/half selectors
    const int la_r = lane & 15;          // A: row within 16
    const int la_h = lane >> 4;          // A: k half (0/1)
    const int lb_r = lane & 7;           // B: row within 8
    const int lb_h = (lane >> 3) & 1;    // B: k half (0/1)

    // prologue: chunks 0,1
    load_chunk(sb,               Ahi, Alo, Bhi, Blo, m0, n0, 0,  tid); CP_COMMIT();
    load_chunk(sb + STAGE_BYTES, Ahi, Alo, Bhi, Blo, m0, n0, 64, tid); CP_COMMIT();

    for (int c = 0; c < 16; c++) {
        const int s = c & 1;
        if (c < 15) { CP_WAIT(1); } else { CP_WAIT(0); }
        __syncthreads();

        const uint32_t stg = sb + s * STAGE_BYTES;
#pragma unroll
        for (int ks = 0; ks < 4; ks++) {
            const int k0 = ks * 16;
            uint32_t ahi[4][4], alo[4][4];
#pragma unroll
            for (int mt = 0; mt < 4; mt++) {
                uint32_t off = SW128((uint32_t)((wm + mt * 16 + la_r) * 128 + (k0 + la_h * 8) * 2));
                ldsm4(ahi[mt], stg + OFF_AHI + off);
                ldsm4(alo[mt], stg + OFF_ALO + off);
            }
            uint32_t bhi[4][2], blo[4][2];
#pragma unroll
            for (int nt = 0; nt < 4; nt++) {
                uint32_t off = SW128((uint32_t)((wn + nt * 8 + lb_r) * 128 + (k0 + lb_h * 8) * 2));
                ldsm2(bhi[nt], stg + OFF_BHI + off);
                ldsm2(blo[nt], stg + OFF_BLO + off);
            }
#pragma unroll
            for (int mt = 0; mt < 4; mt++)
#pragma unroll
                for (int nt = 0; nt < 4; nt++) {
                    mma_bf16(acc[mt][nt], ahi[mt], bhi[nt]);
                    mma_bf16(acc[mt][nt], ahi[mt], blo[nt]);
                    mma_bf16(acc[mt][nt], alo[mt], bhi[nt]);
                }
        }
        __syncthreads();   // everyone done reading stage s
        if (c + 2 < 16) {
            load_chunk(sb + s * STAGE_BYTES, Ahi, Alo, Bhi, Blo, m0, n0, (c + 2) * 64, tid);
            CP_COMMIT();
        }
    }

    // epilogue: c frag -> global fp32
    const int rquad = lane >> 2, cpair = (lane & 3) * 2;
#pragma unroll
    for (int mt = 0; mt < 4; mt++) {
#pragma unroll
        for (int nt = 0; nt < 4; nt++) {
            int row = m0 + wm + mt * 16 + rquad;
            int col = n0 + wn + nt * 8 + cpair;
            float2* p0 = (float2*)(C + (size_t)row * Ncols + col);
            float2* p1 = (float2*)(C + (size_t)(row + 8) * Ncols + col);
            *p0 = make_float2(acc[mt][nt][0], acc[mt][nt][1]);
            *p1 = make_float2(acc[mt][nt][2], acc[mt][nt][3]);
        }
    }
}

// ================= RoPE + ELU feature map =================
__global__ __launch_bounds__(256) void featmap_kernel()
{
    int idx = blockIdx.x * blockDim.x + threadIdx.x;
    int j = idx & 31;
    int h = (idx >> 5) & 15;
    int t = (idx >> 9) & 4095;
    int b = idx >> 21;

    const float* row = g_qkv + (size_t)(b * SEQ + t) * 3072 + h * 64;
    float q1 = row[j],        q2 = row[j + 32];
    float k1 = row[1024 + j], k2 = row[1024 + j + 32];
    float v1 = row[2048 + j], v2 = row[2048 + j + 32];

    float inv = expf(-0.28782313662425572f * (float)j);
    float ang = (float)t * inv;
    float s, c;
    sincosf(ang, &s, &c);

    float qa = q1 * c - q2 * s, qb = q1 * s + q2 * c;
    float ka = k1 * c - k2 * s, kb = k1 * s + k2 * c;

    qa *= FSCALE; qb *= FSCALE; ka *= FSCALE; kb *= FSCALE;
    qa = (qa > 0.f) ? qa + 1.f : expf(qa);
    qb = (qb > 0.f) ? qb + 1.f : expf(qb);
    ka = (ka > 0.f) ? ka + 1.f : expf(ka);
    kb = (kb > 0.f) ? kb + 1.f : expf(kb);

    size_t o = ((size_t)(b * NH + h) * SEQ + t) * 64 + j;
    g_qf[o] = qa; g_qf[o + 32] = qb;
    g_kf[o] = ka; g_kf[o + 32] = kb;
    g_vf[o] = v1; g_vf[o + 32] = v2;
}

// ================= per-chunk local sums =================
__global__ __launch_bounds__(256) void chunksum_kernel()
{
    const int c = blockIdx.x, bh = blockIdx.y;
    const int tid = threadIdx.x;
    __shared__ __align__(16) float ks[CHUNK][HD];
    __shared__ __align__(16) float vs[CHUNK][HD];

    const float* Kg = g_kf + ((size_t)bh * SEQ + c * CHUNK) * HD;
    const float* Vg = g_vf + ((size_t)bh * SEQ + c * CHUNK) * HD;

    const int row = tid >> 2, f0 = tid & 3;
#pragma unroll
    for (int i = 0; i < 4; i++) {
        int f = (f0 + i * 4) * 4;
        *(float4*)&ks[row][f] = *(const float4*)(Kg + row * 64 + f);
        *(float4*)&vs[row][f] = *(const float4*)(Vg + row * 64 + f);
    }
    __syncthreads();

    const int m = tid & 63;
    const int dbase = (tid >> 6) * 16;
    float acc[16];
#pragma unroll
    for (int i = 0; i < 16; i++) acc[i] = 0.f;

    for (int t = 0; t < CHUNK; t++) {
        float v = vs[t][m];
#pragma unroll
        for (int w = 0; w < 4; w++) {
            float4 kk = *(float4*)&ks[t][dbase + w * 4];
            acc[w * 4 + 0] += kk.x * v;
            acc[w * 4 + 1] += kk.y * v;
            acc[w * 4 + 2] += kk.z * v;
            acc[w * 4 + 3] += kk.w * v;
        }
    }

    float* S = g_Skv + ((size_t)bh * NCHUNK + c) * (HD * HD);
#pragma unroll
    for (int d = 0; d < 16; d++)
        S[(dbase + d) * 64 + m] = acc[d];

    if (tid < 64) {
        float s = 0.f;
        for (int t = 0; t < CHUNK; t++) s += ks[t][tid];
        g_Sks[((size_t)bh * NCHUNK + c) * HD + tid] = s;
    }
}

// ================= exclusive prefixes (one thread per chain) =================
__global__ __launch_bounds__(256) void prefix_kernel()
{
    int e = blockIdx.x * 256 + threadIdx.x;     // BH*4096 chains
    int bh = e >> 12, el = e & 4095;
    float run = 0.f;
    for (int c = 0; c < NCHUNK; c++) {
        size_t i = ((size_t)bh * NCHUNK + c) * (HD * HD) + el;
        g_Pkv[i] = run;
        run += g_Skv[i];
    }
}
__global__ __launch_bounds__(256) void prefix_ks_kernel()
{
    int e = blockIdx.x * 256 + threadIdx.x;     // BH*64 chains
    int bh = e >> 6, d = e & 63;
    float run = 0.f;
    for (int c = 0; c < NCHUNK; c++) {
        size_t i = ((size_t)bh * NCHUNK + c) * HD + d;
        g_Pks[i] = run;
        run += g_Sks[i];
    }
}

// ================= chunk attention (epilogue writes bf16 hi/lo) =================
__global__ __launch_bounds__(256) void attn_kernel()
{
    const int c = blockIdx.x, bh = blockIdx.y;
    const int tid = threadIdx.x;
    extern __shared__ float sm[];
    float* Qt   = sm;
    float* Kt   = Qt + 64 * 68;
    float* At   = Kt + 64 * 68;
    float* Vs   = At + 64 * 68;
    float* Ps   = Vs + 64 * 64;
    float* pks  = Ps + 64 * 64;
    float* dinv = pks + 64;

    const int t0 = c * CHUNK;
    const float* Qg   = g_qf + ((size_t)bh * SEQ + t0) * HD;
    const float* Kg   = g_kf + ((size_t)bh * SEQ + t0) * HD;
    const float* Vg   = g_vf + ((size_t)bh * SEQ + t0) * HD;
    const float* Pg   = g_Pkv + ((size_t)bh * NCHUNK + c) * (HD * HD);
    const float* pksg = g_Pks + ((size_t)bh * NCHUNK + c) * HD;

    const int row = tid >> 2, f0 = tid & 3;
#pragma unroll
    for (int i = 0; i < 4; i++) {
        int d = (f0 + i * 4) * 4;
        float4 q4 = *(const float4*)(Qg + row * 64 + d);
        Qt[(d + 0) * 68 + row] = q4.x;
        Qt[(d + 1) * 68 + row] = q4.y;
        Qt[(d + 2) * 68 + row] = q4.z;
        Qt[(d + 3) * 68 + row] = q4.w;
        float4 k4 = *(const float4*)(Kg + row * 64 + d);
        Kt[(d + 0) * 68 + row] = k4.x;
        Kt[(d + 1) * 68 + row] = k4.y;
        Kt[(d + 2) * 68 + row] = k4.z;
        Kt[(d + 3) * 68 + row] = k4.w;
        *(float4*)&Vs[row * 64 + d] = *(const float4*)(Vg + row * 64 + d);
        *(float4*)&Ps[row * 64 + d] = *(const float4*)(Pg + row * 64 + d);
    }
    if (tid < 64) pks[tid] = pksg[tid];
    __syncthreads();

    const int ty = tid >> 4, tx = tid & 15;
    const int rb = ty * 4, cb = tx * 4;

    float a[4][4];
#pragma unroll
    for (int i = 0; i < 4; i++)
#pragma unroll
        for (int j = 0; j < 4; j++) a[i][j] = 0.f;

    for (int d = 0; d < 64; d++) {
        float4 q4 = *(float4*)&Qt[d * 68 + rb];
        float4 k4 = *(float4*)&Kt[d * 68 + cb];
        float qv[4] = {q4.x, q4.y, q4.z, q4.w};
        float kv[4] = {k4.x, k4.y, k4.z, k4.w};
#pragma unroll
        for (int i = 0; i < 4; i++)
#pragma unroll
            for (int j = 0; j < 4; j++)
                a[i][j] += qv[i] * kv[j];
    }
#pragma unroll
    for (int i = 0; i < 4; i++)
#pragma unroll
        for (int j = 0; j < 4; j++) {
            int ti = rb + i, tj = cb + j;
            At[tj * 68 + ti] = (tj <= ti) ? a[i][j] : 0.f;
        }
    __syncthreads();

    if (tid < 64) {
        float s = 0.f;
        for (int tj = 0; tj < 64; tj++) s += At[tj * 68 + tid];
        for (int d = 0; d < 64; d++) s += Qt[d * 68 + tid] * pks[d];
        dinv[tid] = 1.0f / fmaxf(s, 1e-6f);
    }
    __syncthreads();

    float o[4][4];
#pragma unroll
    for (int i = 0; i < 4; i++)
#pragma unroll
        for (int j = 0; j < 4; j++) o[i][j] = 0.f;

    for (int tj = 0; tj < 64; tj++) {
        float4 a4 = *(float4*)&At[tj * 68 + rb];
        float4 v4 = *(float4*)&Vs[tj * 64 + cb];
        float av[4] = {a4.x, a4.y, a4.z, a4.w};
        float vv[4] = {v4.x, v4.y, v4.z, v4.w};
#pragma unroll
        for (int i = 0; i < 4; i++)
#pragma unroll
            for (int j = 0; j < 4; j++)
                o[i][j] += av[i] * vv[j];
    }
    for (int d = 0; d < 64; d++) {
        float4 q4 = *(float4*)&Qt[d * 68 + rb];
        float4 p4 = *(float4*)&Ps[d * 64 + cb];
        float qv[4] = {q4.x, q4.y, q4.z, q4.w};
        float pv[4] = {p4.x, p4.y, p4.z, p4.w};
#pragma unroll
        for (int i = 0; i < 4; i++)
#pragma unroll
            for (int j = 0; j < 4; j++)
                o[i][j] += qv[i] * pv[j];
    }

    const int b = bh >> 4, h = bh & 15;
#pragma unroll
    for (int i = 0; i < 4; i++) {
        int ti = rb + i;
        float di = dinv[ti];
        __nv_bfloat16 hv[4], lv[4];
#pragma unroll
        for (int j = 0; j < 4; j++) {
            float v = o[i][j] * di;
            hv[j] = __float2bfloat16(v);
            lv[j] = __float2bfloat16(v - __bfloat162float(hv[j]));
        }
        size_t oidx = (size_t)(b * SEQ + t0 + ti) * DIM + h * 64 + cb;
        *(uint2*)(g_ahi + oidx) = *(uint2*)hv;
        *(uint2*)(g_alo + oidx) = *(uint2*)lv;
    }
}

// ================= launch =================
extern "C" void kernel_launch(void* const* d_in, const int* in_sizes, int n_in,
                              void* d_out, int out_size)
{
    const float* x     = (const float*)d_in[0];
    const float* w_qkv = (const float*)d_in[1];
    const float* w_out = (const float*)d_in[2];
    float* out = (float*)d_out;

    float* qkv;             cudaGetSymbolAddress((void**)&qkv,  g_qkv);
    __nv_bfloat16 *xhi, *xlo, *wqhi, *wqlo, *wohi, *wolo, *ahi, *alo;
    cudaGetSymbolAddress((void**)&xhi,  g_xhi);
    cudaGetSymbolAddress((void**)&xlo,  g_xlo);
    cudaGetSymbolAddress((void**)&wqhi, g_wqhi);
    cudaGetSymbolAddress((void**)&wqlo, g_wqlo);
    cudaGetSymbolAddress((void**)&wohi, g_wohi);
    cudaGetSymbolAddress((void**)&wolo, g_wolo);
    cudaGetSymbolAddress((void**)&ahi,  g_ahi);
    cudaGetSymbolAddress((void**)&alo,  g_alo);

    cudaFuncSetAttribute(gemm_tc, cudaFuncAttributeMaxDynamicSharedMemorySize, GEMM_SMEM);
    const int attn_smem = (64 * 68 * 3 + 64 * 64 * 2 + 128) * 4;
    cudaFuncSetAttribute(attn_kernel, cudaFuncAttributeMaxDynamicSharedMemorySize, attn_smem);

    // 0) splits
    split_kernel<<<(MTOT * DIM) / (256 * 4), 256>>>(x, xhi, xlo);
    tsplit_kernel<<<dim3(3 * DIM / 32, DIM / 32), dim3(32, 8)>>>(w_qkv, wqhi, wqlo, DIM, 3 * DIM);
    tsplit_kernel<<<dim3(DIM / 32, DIM / 32), dim3(32, 8)>>>(w_out, wohi, wolo, DIM, DIM);

    // 1) QKV projection on tensor cores (mma.sync bf16x3)
    gemm_tc<<<dim3(3 * DIM / 128, MTOT / 128), 256, GEMM_SMEM>>>(xhi, xlo, wqhi, wqlo, qkv, 3 * DIM);

    // 2) RoPE + ELU feature map
    featmap_kernel<<<(BATCH * SEQ * NH * 32) / 256, 256>>>();

    // 3) per-chunk K^T V and sum(k)
    chunksum_kernel<<<dim3(NCHUNK, BH), 256>>>();

    // 4) exclusive prefixes
    prefix_kernel<<<(BH * HD * HD) / 256, 256>>>();
    prefix_ks_kernel<<<(BH * HD) / 256, 256>>>();

    // 5) chunk attention -> bf16 hi/lo activations
    attn_kernel<<<dim3(NCHUNK, BH), 256, attn_smem>>>();

    // 6) output projection on tensor cores
    gemm_tc<<<dim3(DIM / 128, MTOT / 128), 256, GEMM_SMEM>>>(ahi, alo, wohi, wolo, out, DIM);
}